// round 15
// baseline (speedup 1.0000x reference)
#include <cuda_runtime.h>
#include <cstdint>

// Problem shape (fixed)
#define BATCH 64
#define TT    2048
#define DD    256
#define HH    256

// Packed fp32x2 ops (sm_100+ PTX; ptxas never emits these from C++)
#define FMA2(acc, a, b) \
    asm("fma.rn.f32x2 %0, %1, %2, %0;" : "+l"(acc) : "l"(a), "l"(b))
#define SPLAT2(dst, s) \
    asm("mov.b64 %0, {%1, %1};" : "=l"(dst) : "f"(s))
#define PACK2(dst, lo, hi) \
    asm("mov.b64 %0, {%1, %2};" : "=l"(dst) : "f"(lo), "f"(hi))
#define UNPACK2(lo, hi, src) \
    asm("mov.b64 {%0, %1}, %2;" : "=f"(lo), "=f"(hi) : "l"(src))

__device__ __forceinline__ uint32_t smem_u32(const void* p) {
    uint32_t a;
    asm("{ .reg .u64 t; cvta.to.shared.u64 t, %1; cvt.u32.u64 %0, t; }"
        : "=r"(a) : "l"(p));
    return a;
}

// Fast tanh: v = 1 - 2/(e^{2x}+1). MUFU-based, branch-free, saturates to +-1.
__device__ __forceinline__ float fast_tanh(float x) {
    float e = __expf(2.0f * x);
    return 1.0f - __fdividef(2.0f, e + 1.0f);
}

// ---------------------------------------------------------------------------
// Kernel A: xp = x @ Wxh + bias   (M=B*T, K=D, N=H), f32x2 inner product
// ---------------------------------------------------------------------------
#define BM 128
#define BN 128
#define BK 8
#define TM 8
#define TN 8

__global__ __launch_bounds__(256) void xp_gemm_kernel(
    const float* __restrict__ X,
    const float* __restrict__ W,
    const float* __restrict__ bias,
    float* __restrict__ out)
{
    __shared__ float As[BK][BM];
    __shared__ __align__(16) float Bs[BK][BN];

    const int m0 = blockIdx.x * BM;
    const int n0 = blockIdx.y * BN;
    const int tid = threadIdx.x;
    const int tx = tid & 15;   // N
    const int ty = tid >> 4;   // M

    const int a_r = tid >> 1;
    const int a_k = (tid & 1) * 4;
    const int b_r = tid >> 5;
    const int b_n = (tid & 31) * 4;

    unsigned long long acc[TM][TN / 2];
#pragma unroll
    for (int i = 0; i < TM; i++)
#pragma unroll
        for (int j = 0; j < TN / 2; j++) acc[i][j] = 0ull;

    const float* Xp = X + (long long)m0 * DD;

    for (int k0 = 0; k0 < DD; k0 += BK) {
        float4 av = *reinterpret_cast<const float4*>(Xp + (long long)a_r * DD + k0 + a_k);
        As[a_k + 0][a_r] = av.x;
        As[a_k + 1][a_r] = av.y;
        As[a_k + 2][a_r] = av.z;
        As[a_k + 3][a_r] = av.w;
        float4 bv = *reinterpret_cast<const float4*>(W + (long long)(k0 + b_r) * HH + n0 + b_n);
        *reinterpret_cast<float4*>(&Bs[b_r][b_n]) = bv;
        __syncthreads();

#pragma unroll
        for (int k = 0; k < BK; k++) {
            ulonglong2 b01 = *reinterpret_cast<const ulonglong2*>(&Bs[k][tx * TN]);
            ulonglong2 b23 = *reinterpret_cast<const ulonglong2*>(&Bs[k][tx * TN + 4]);
            float ar[TM];
#pragma unroll
            for (int i = 0; i < TM; i++) ar[i] = As[k][ty * TM + i];
#pragma unroll
            for (int i = 0; i < TM; i++) {
                unsigned long long ai;
                SPLAT2(ai, ar[i]);
                FMA2(acc[i][0], ai, b01.x);
                FMA2(acc[i][1], ai, b01.y);
                FMA2(acc[i][2], ai, b23.x);
                FMA2(acc[i][3], ai, b23.y);
            }
        }
        __syncthreads();
    }

    float bv[TN];
#pragma unroll
    for (int j = 0; j < TN; j++) bv[j] = bias[n0 + tx * TN + j];

#pragma unroll
    for (int i = 0; i < TM; i++) {
        const int row = m0 + ty * TM + i;
        float* op = out + (long long)row * HH + n0 + tx * TN;
        float r[TN];
#pragma unroll
        for (int j = 0; j < TN / 2; j++) {
            UNPACK2(r[2 * j], r[2 * j + 1], acc[i][j]);
        }
        float4 r0, r1;
        r0.x = r[0] + bv[0]; r0.y = r[1] + bv[1];
        r0.z = r[2] + bv[2]; r0.w = r[3] + bv[3];
        r1.x = r[4] + bv[4]; r1.y = r[5] + bv[5];
        r1.z = r[6] + bv[6]; r1.w = r[7] + bv[7];
        *reinterpret_cast<float4*>(op)     = r0;
        *reinterpret_cast<float4*>(op + 4) = r1;
    }
}

// ---------------------------------------------------------------------------
// Kernel B: recurrence on a 2-CTA cluster per batch element.
//   rank r owns output columns [r*128, (r+1)*128)
//   512 threads: col = tid>>2 (0..127), kh = tid&3 (4-way k-split; the four
//   kh lanes of a column are adjacent lanes of one warp)
//   thread (col,kh) weights (8+8 f32x2 pairs = 64 regs; cap 128 @512thr):
//     Phase A: k in [rank*128 + kh*32, +32)   (local half of h)
//     Phase B: k in [peer*128 + kh*32, +32)   (peer half of h)
//
// Cross-CTA sync: st.async + mbarrier complete_tx (proven in R12).
//   - 4 mbarriers; mbar[t&3] guards the peer half of hbuf[t&1] for step t.
//   - kh3 threads st.async h_{t+1} into the peer's hbuf[(t+1)&1], signaling
//     the peer's mbar[(t+1)&3] with 4B tx each (128 stores = 512B).
//   - tid0 re-arms mbar[t&3] after the stores, for reuse at t+4; mbars 1..3
//     pre-armed, mbar[0] armed at t=0 (first completion t=4, phase 0).
//   - PARITY: mbar[i!=0] first completes at t=i (ph0) -> par=(t>>2)&1.
//             mbar[0]   first completes at t=4 (ph0) -> par=((t>>2)+1)&1.
// Per step: PhaseA (overlaps peer store flight) -> wait -> PhaseB ->
//   2x shfl combine -> fast_tanh -> stores (kh0 local / kh1 gmem /
//   kh3 st.async) -> arm -> syncthreads.
// ---------------------------------------------------------------------------
#define QPAIRS 8    // 32 rows per phase -> 8 f32x2 pairs... per k-quarter

__global__ __launch_bounds__(512, 1) __cluster_dims__(2, 1, 1)
void rnn_rec_kernel(
    const float* __restrict__ Whh,
    float* __restrict__ out)
{
    __shared__ __align__(16) float hbuf[2][HH];
    __shared__ __align__(8) unsigned long long mbars[4];

    const int tid = threadIdx.x;
    const int c   = tid >> 2;
    const int kh  = tid & 3;
    uint32_t rank;
    asm("mov.u32 %0, %%cluster_ctarank;" : "=r"(rank));
    const int batch = blockIdx.x >> 1;
    const int gcol  = (int)rank * 128 + c;

    const int kbaseA = (int)rank * 128 + kh * 32;         // local-half slice
    const int kbaseB = (int)(rank ^ 1u) * 128 + kh * 32;  // peer-half slice

    // ---- one-time: register-resident Whh slices (16 pairs = 32 regs ea) ----
    unsigned long long wpA[QPAIRS * 2], wpB[QPAIRS * 2];
#pragma unroll
    for (int p = 0; p < QPAIRS * 2; p++) {
        float a0 = Whh[(kbaseA + 2 * p + 0) * HH + gcol];
        float a1 = Whh[(kbaseA + 2 * p + 1) * HH + gcol];
        PACK2(wpA[p], a0, a1);
        float b0 = Whh[(kbaseB + 2 * p + 0) * HH + gcol];
        float b1 = Whh[(kbaseB + 2 * p + 1) * HH + gcol];
        PACK2(wpB[p], b0, b1);
    }

    const uint32_t mb0_local = smem_u32(&mbars[0]);
    const uint32_t hb_local  = smem_u32(&hbuf[0][0]);

    if (tid == 0) {
#pragma unroll
        for (int i = 0; i < 4; i++) {
            asm volatile("mbarrier.init.shared.b64 [%0], %1;"
                         :: "r"(mb0_local + 8u * i), "r"(1) : "memory");
        }
        // pre-arm mbars for steps t=1,2,3; mbar[0] armed in-loop at t=0
#pragma unroll
        for (int i = 1; i < 4; i++) {
            asm volatile("mbarrier.arrive.expect_tx.shared.b64 _, [%0], %1;"
                         :: "r"(mb0_local + 8u * i), "r"(512) : "memory");
        }
    }
    if (tid < HH) hbuf[0][tid] = 0.f;
    if (tid >= 512 - HH) hbuf[1][tid - (512 - HH)] = 0.f;  // benign init
    __syncthreads();
    asm volatile("barrier.cluster.arrive.aligned;" ::: "memory");
    asm volatile("barrier.cluster.wait.aligned;" ::: "memory");

    uint32_t mb0_peer, hb_peer;
    {
        uint32_t peer = rank ^ 1u;
        asm("mapa.shared::cluster.u32 %0, %1, %2;"
            : "=r"(mb0_peer) : "r"(mb0_local), "r"(peer));
        asm("mapa.shared::cluster.u32 %0, %1, %2;"
            : "=r"(hb_peer) : "r"(hb_local), "r"(peer));
    }

    float* orow = out + (long long)batch * TT * HH;
    float xpv = orow[gcol];
    int cur = 0;

#pragma unroll 1
    for (int t = 0; t < TT; t++) {
        float xnext = 0.f;
        if (t + 1 < TT) xnext = orow[(t + 1) * HH + gcol];

        unsigned long long a0 = 0ull, a1 = 0ull, a2 = 0ull, a3 = 0ull;

        // ---- Phase A: local quarter of h (overlaps peer's store flight) ----
        {
            const ulonglong2* h2 =
                reinterpret_cast<const ulonglong2*>(&hbuf[cur][kbaseA]);
#pragma unroll
            for (int j = 0; j < 4; j++) {          // 4 iters: 2 LDS.128 + 4 FMA2
                ulonglong2 hA = h2[2 * j];
                ulonglong2 hB = h2[2 * j + 1];
                FMA2(a0, hA.x, wpA[4 * j + 0]);
                FMA2(a1, hA.y, wpA[4 * j + 1]);
                FMA2(a2, hB.x, wpA[4 * j + 2]);
                FMA2(a3, hB.y, wpA[4 * j + 3]);
            }
        }

        // ---- wait: peer half of h_t landed (tx complete). t=0: local init.
        const uint32_t mb_t = mb0_local + 8u * (uint32_t)(t & 3);
        if (t > 0) {
            const uint32_t q = (uint32_t)(t >> 2);
            const uint32_t par = ((t & 3) == 0) ? ((q + 1) & 1u) : (q & 1u);
            uint32_t done;
            asm volatile(
                "{\n\t.reg .pred p;\n\t"
                "mbarrier.try_wait.parity.acquire.cluster.shared::cta.b64 p, [%1], %2;\n\t"
                "selp.b32 %0, 1, 0, p;\n\t}"
                : "=r"(done) : "r"(mb_t), "r"(par) : "memory");
            if (!done) {
                asm volatile(
                    "{\n\t.reg .pred P1;\n\t"
                    "WL_%=:\n\t"
                    "mbarrier.try_wait.parity.acquire.cluster.shared::cta.b64 P1, [%0], %1, 0x989680;\n\t"
                    "@P1 bra.uni WD_%=;\n\t"
                    "bra.uni WL_%=;\n\t"
                    "WD_%=:\n\t}"
                    :: "r"(mb_t), "r"(par) : "memory");
            }
        }

        // ---- Phase B: peer quarter of h ----
        {
            const ulonglong2* h2 =
                reinterpret_cast<const ulonglong2*>(&hbuf[cur][kbaseB]);
#pragma unroll
            for (int j = 0; j < 4; j++) {
                ulonglong2 hA = h2[2 * j];
                ulonglong2 hB = h2[2 * j + 1];
                FMA2(a0, hA.x, wpB[4 * j + 0]);
                FMA2(a1, hA.y, wpB[4 * j + 1]);
                FMA2(a2, hB.x, wpB[4 * j + 2]);
                FMA2(a3, hB.y, wpB[4 * j + 3]);
            }
        }

        float s0, s1, s2, s3, s4, s5, s6, s7;
        UNPACK2(s0, s1, a0);
        UNPACK2(s2, s3, a1);
        UNPACK2(s4, s5, a2);
        UNPACK2(s6, s7, a3);
        float s = ((s0 + s1) + (s2 + s3)) + ((s4 + s5) + (s6 + s7));
        // combine the 4 kh lanes (adjacent lanes of one warp)
        s += __shfl_xor_sync(0xffffffffu, s, 1);
        s += __shfl_xor_sync(0xffffffffu, s, 2);

        const int nxt = cur ^ 1;
        float v = fast_tanh(xpv + s);

        if (kh == 0) {
            hbuf[nxt][gcol] = v;                   // local half for t+1
        } else if (kh == 1) {
            orow[t * HH + gcol] = v;               // h_t to gmem
        } else if (kh == 3) {
            if (t + 1 < TT) {
                uint32_t dst = hb_peer + (uint32_t)(nxt * HH + gcol) * 4u;
                uint32_t mbp = mb0_peer + 8u * (uint32_t)((t + 1) & 3);
                asm volatile(
                    "st.async.shared::cluster.mbarrier::complete_tx::bytes.b32 [%0], %1, [%2];"
                    :: "r"(dst), "f"(v), "r"(mbp) : "memory");
            }
        }

        // re-arm mbar[t&3] for its reuse at step t+4 (off the wake path)
        if (tid == 0) {
            asm volatile("mbarrier.arrive.expect_tx.shared.b64 _, [%0], %1;"
                         :: "r"(mb_t), "r"(512) : "memory");
        }
        __syncthreads();                           // local half published

        cur = nxt;
        xpv = xnext;
    }

    // teardown: keep smem alive until the peer is fully done
    asm volatile("barrier.cluster.arrive.aligned;" ::: "memory");
    asm volatile("barrier.cluster.wait.aligned;" ::: "memory");
}

// ---------------------------------------------------------------------------
extern "C" void kernel_launch(void* const* d_in, const int* in_sizes, int n_in,
                              void* d_out, int out_size)
{
    const float* x    = (const float*)d_in[0];
    const float* Wxh  = (const float*)d_in[1];
    const float* Whh  = (const float*)d_in[2];
    const float* bias = (const float*)d_in[3];
    float* out = (float*)d_out;

    const int M = in_sizes[0] / DD;   // B*T

    dim3 gridA(M / BM, HH / BN);
    xp_gemm_kernel<<<gridA, 256>>>(x, Wxh, bias, out);

    rnn_rec_kernel<<<BATCH * 2, 512>>>(Whh, out);
}

// round 16
// speedup vs baseline: 1.7109x; 1.7109x over previous
#include <cuda_runtime.h>
#include <cstdint>

// Problem shape (fixed)
#define BATCH 64
#define TT    2048
#define DD    256
#define HH    256

// Packed fp32x2 ops (sm_100+ PTX; ptxas never emits these from C++)
#define FMA2(acc, a, b) \
    asm("fma.rn.f32x2 %0, %1, %2, %0;" : "+l"(acc) : "l"(a), "l"(b))
#define SPLAT2(dst, s) \
    asm("mov.b64 %0, {%1, %1};" : "=l"(dst) : "f"(s))
#define PACK2(dst, lo, hi) \
    asm("mov.b64 %0, {%1, %2};" : "=l"(dst) : "f"(lo), "f"(hi))
#define UNPACK2(lo, hi, src) \
    asm("mov.b64 {%0, %1}, %2;" : "=f"(lo), "=f"(hi) : "l"(src))

__device__ __forceinline__ uint32_t smem_u32(const void* p) {
    uint32_t a;
    asm("{ .reg .u64 t; cvta.to.shared.u64 t, %1; cvt.u32.u64 %0, t; }"
        : "=r"(a) : "l"(p));
    return a;
}

// Fast tanh: v = 1 - 2/(e^{2x}+1). MUFU-based, branch-free, saturates to +-1.
__device__ __forceinline__ float fast_tanh(float x) {
    float e = __expf(2.0f * x);
    return 1.0f - __fdividef(2.0f, e + 1.0f);
}

// ---------------------------------------------------------------------------
// Kernel A: xp = x @ Wxh + bias   (M=B*T, K=D, N=H), f32x2 inner product
// ---------------------------------------------------------------------------
#define BM 128
#define BN 128
#define BK 8
#define TM 8
#define TN 8

__global__ __launch_bounds__(256) void xp_gemm_kernel(
    const float* __restrict__ X,
    const float* __restrict__ W,
    const float* __restrict__ bias,
    float* __restrict__ out)
{
    __shared__ float As[BK][BM];
    __shared__ __align__(16) float Bs[BK][BN];

    const int m0 = blockIdx.x * BM;
    const int n0 = blockIdx.y * BN;
    const int tid = threadIdx.x;
    const int tx = tid & 15;   // N
    const int ty = tid >> 4;   // M

    const int a_r = tid >> 1;
    const int a_k = (tid & 1) * 4;
    const int b_r = tid >> 5;
    const int b_n = (tid & 31) * 4;

    unsigned long long acc[TM][TN / 2];
#pragma unroll
    for (int i = 0; i < TM; i++)
#pragma unroll
        for (int j = 0; j < TN / 2; j++) acc[i][j] = 0ull;

    const float* Xp = X + (long long)m0 * DD;

    for (int k0 = 0; k0 < DD; k0 += BK) {
        float4 av = *reinterpret_cast<const float4*>(Xp + (long long)a_r * DD + k0 + a_k);
        As[a_k + 0][a_r] = av.x;
        As[a_k + 1][a_r] = av.y;
        As[a_k + 2][a_r] = av.z;
        As[a_k + 3][a_r] = av.w;
        float4 bv = *reinterpret_cast<const float4*>(W + (long long)(k0 + b_r) * HH + n0 + b_n);
        *reinterpret_cast<float4*>(&Bs[b_r][b_n]) = bv;
        __syncthreads();

#pragma unroll
        for (int k = 0; k < BK; k++) {
            ulonglong2 b01 = *reinterpret_cast<const ulonglong2*>(&Bs[k][tx * TN]);
            ulonglong2 b23 = *reinterpret_cast<const ulonglong2*>(&Bs[k][tx * TN + 4]);
            float ar[TM];
#pragma unroll
            for (int i = 0; i < TM; i++) ar[i] = As[k][ty * TM + i];
#pragma unroll
            for (int i = 0; i < TM; i++) {
                unsigned long long ai;
                SPLAT2(ai, ar[i]);
                FMA2(acc[i][0], ai, b01.x);
                FMA2(acc[i][1], ai, b01.y);
                FMA2(acc[i][2], ai, b23.x);
                FMA2(acc[i][3], ai, b23.y);
            }
        }
        __syncthreads();
    }

    float bv[TN];
#pragma unroll
    for (int j = 0; j < TN; j++) bv[j] = bias[n0 + tx * TN + j];

#pragma unroll
    for (int i = 0; i < TM; i++) {
        const int row = m0 + ty * TM + i;
        float* op = out + (long long)row * HH + n0 + tx * TN;
        float r[TN];
#pragma unroll
        for (int j = 0; j < TN / 2; j++) {
            UNPACK2(r[2 * j], r[2 * j + 1], acc[i][j]);
        }
        float4 r0, r1;
        r0.x = r[0] + bv[0]; r0.y = r[1] + bv[1];
        r0.z = r[2] + bv[2]; r0.w = r[3] + bv[3];
        r1.x = r[4] + bv[4]; r1.y = r[5] + bv[5];
        r1.z = r[6] + bv[6]; r1.w = r[7] + bv[7];
        *reinterpret_cast<float4*>(op)     = r0;
        *reinterpret_cast<float4*>(op + 4) = r1;
    }
}

// ---------------------------------------------------------------------------
// Kernel B: recurrence, 2-CTA cluster per PAIR of batch elements.
// R12 layout (2-way kh split, 256 threads, proven 1882us) + dual-stream
// interleave: the cluster advances TWO independent batches per loop
// iteration, reusing the SAME Whh weight registers for both.
//
//   rank r owns output columns [r*128, (r+1)*128) of both batches
//   256 threads: col = tid>>1 (0..127), kh = tid&1 (pair = adjacent lanes)
//   weights (shared by both streams): 32+32 f32x2 pairs = 128 regs
//     Phase A: k in [rank*128 + kh*64, +64)   (local half of h)
//     Phase B: k in [peer*128 + kh*64, +64)   (peer half of h)
//
// Cross-CTA sync: st.async + mbarrier complete_tx (R12 protocol), one wait
// per iteration covering BOTH streams: tx = 2 * 128 * 4B = 1024B.
//   - 4 mbarriers; mbar[t&3] guards the peer halves of both streams' h(t).
//   - PARITY: mbar[i!=0] first completes at t=i (ph0) -> par=(t>>2)&1.
//             mbar[0]   first completes at t=4 (ph0) -> par=((t>>2)+1)&1.
// Per iter: PhaseA(s0)+PhaseA(s1) -> wait -> PhaseB(s0)+PhaseB(s1) ->
//   shfl combine x2 -> tanh x2 -> stores (kh0 local / kh1 st.async+gmem)
//   -> arm -> syncthreads.
// ---------------------------------------------------------------------------
#define QPAIRS 32   // 64 rows per phase -> 32 f32x2 pairs

__global__ __launch_bounds__(256, 1) __cluster_dims__(2, 1, 1)
void rnn_rec_kernel(
    const float* __restrict__ Whh,
    float* __restrict__ out)
{
    // hbuf[stream][buf][col]
    __shared__ __align__(16) float hbuf[2][2][HH];
    __shared__ __align__(8) unsigned long long mbars[4];

    const int tid = threadIdx.x;
    const int c   = tid >> 1;
    const int kh  = tid & 1;
    uint32_t rank;
    asm("mov.u32 %0, %%cluster_ctarank;" : "=r"(rank));
    const int pair = blockIdx.x >> 1;          // cluster id: batches 2p, 2p+1
    const int gcol = (int)rank * 128 + c;

    const int kbaseA = (int)rank * 128 + kh * 64;
    const int kbaseB = (int)(rank ^ 1u) * 128 + kh * 64;

    // ---- one-time: register-resident Whh slices (shared by both streams) --
    unsigned long long wpA[QPAIRS], wpB[QPAIRS];
#pragma unroll
    for (int p = 0; p < QPAIRS; p++) {
        float a0 = Whh[(kbaseA + 2 * p + 0) * HH + gcol];
        float a1 = Whh[(kbaseA + 2 * p + 1) * HH + gcol];
        PACK2(wpA[p], a0, a1);
        float b0 = Whh[(kbaseB + 2 * p + 0) * HH + gcol];
        float b1 = Whh[(kbaseB + 2 * p + 1) * HH + gcol];
        PACK2(wpB[p], b0, b1);
    }

    const uint32_t mb0_local = smem_u32(&mbars[0]);
    const uint32_t hb_local  = smem_u32(&hbuf[0][0][0]);

    if (tid == 0) {
#pragma unroll
        for (int i = 0; i < 4; i++) {
            asm volatile("mbarrier.init.shared.b64 [%0], %1;"
                         :: "r"(mb0_local + 8u * i), "r"(1) : "memory");
        }
        // pre-arm mbars for t=1,2,3; mbar[0] armed in-loop at t=0
#pragma unroll
        for (int i = 1; i < 4; i++) {
            asm volatile("mbarrier.arrive.expect_tx.shared.b64 _, [%0], %1;"
                         :: "r"(mb0_local + 8u * i), "r"(1024) : "memory");
        }
    }
    hbuf[0][0][tid] = 0.f;      // stream 0, buf 0 (256 threads cover 256)
    hbuf[1][0][tid] = 0.f;      // stream 1, buf 0
    __syncthreads();
    asm volatile("barrier.cluster.arrive.aligned;" ::: "memory");
    asm volatile("barrier.cluster.wait.aligned;" ::: "memory");

    uint32_t mb0_peer, hb_peer;
    {
        uint32_t peer = rank ^ 1u;
        asm("mapa.shared::cluster.u32 %0, %1, %2;"
            : "=r"(mb0_peer) : "r"(mb0_local), "r"(peer));
        asm("mapa.shared::cluster.u32 %0, %1, %2;"
            : "=r"(hb_peer) : "r"(hb_local), "r"(peer));
    }

    float* orow0 = out + (long long)(2 * pair + 0) * TT * HH;
    float* orow1 = out + (long long)(2 * pair + 1) * TT * HH;
    float xpv0 = orow0[gcol];
    float xpv1 = orow1[gcol];
    int cur = 0;

#pragma unroll 1
    for (int t = 0; t < TT; t++) {
        float xn0 = 0.f, xn1 = 0.f;
        if (t + 1 < TT) {
            xn0 = orow0[(t + 1) * HH + gcol];
            xn1 = orow1[(t + 1) * HH + gcol];
        }

        unsigned long long p0 = 0ull, p1 = 0ull, p2 = 0ull, p3 = 0ull;  // s0
        unsigned long long q0 = 0ull, q1 = 0ull, q2 = 0ull, q3 = 0ull;  // s1

        // ---- Phase A: local halves, both streams (overlap store flight) ---
        {
            const ulonglong2* h0 =
                reinterpret_cast<const ulonglong2*>(&hbuf[0][cur][kbaseA]);
            const ulonglong2* h1 =
                reinterpret_cast<const ulonglong2*>(&hbuf[1][cur][kbaseA]);
#pragma unroll
            for (int j = 0; j < QPAIRS / 4; j++) {   // 8 iters
                ulonglong2 hA0 = h0[2 * j];
                ulonglong2 hB0 = h0[2 * j + 1];
                ulonglong2 hA1 = h1[2 * j];
                ulonglong2 hB1 = h1[2 * j + 1];
                FMA2(p0, hA0.x, wpA[4 * j + 0]);
                FMA2(q0, hA1.x, wpA[4 * j + 0]);
                FMA2(p1, hA0.y, wpA[4 * j + 1]);
                FMA2(q1, hA1.y, wpA[4 * j + 1]);
                FMA2(p2, hB0.x, wpA[4 * j + 2]);
                FMA2(q2, hB1.x, wpA[4 * j + 2]);
                FMA2(p3, hB0.y, wpA[4 * j + 3]);
                FMA2(q3, hB1.y, wpA[4 * j + 3]);
            }
        }

        // ---- wait: both streams' peer halves landed. t=0: local init. ----
        const uint32_t mb_t = mb0_local + 8u * (uint32_t)(t & 3);
        if (t > 0) {
            const uint32_t q = (uint32_t)(t >> 2);
            const uint32_t par = ((t & 3) == 0) ? ((q + 1) & 1u) : (q & 1u);
            uint32_t done;
            asm volatile(
                "{\n\t.reg .pred p;\n\t"
                "mbarrier.try_wait.parity.acquire.cluster.shared::cta.b64 p, [%1], %2;\n\t"
                "selp.b32 %0, 1, 0, p;\n\t}"
                : "=r"(done) : "r"(mb_t), "r"(par) : "memory");
            if (!done) {
                asm volatile(
                    "{\n\t.reg .pred P1;\n\t"
                    "WL_%=:\n\t"
                    "mbarrier.try_wait.parity.acquire.cluster.shared::cta.b64 P1, [%0], %1, 0x989680;\n\t"
                    "@P1 bra.uni WD_%=;\n\t"
                    "bra.uni WL_%=;\n\t"
                    "WD_%=:\n\t}"
                    :: "r"(mb_t), "r"(par) : "memory");
            }
        }

        // ---- Phase B: peer halves, both streams ----
        {
            const ulonglong2* h0 =
                reinterpret_cast<const ulonglong2*>(&hbuf[0][cur][kbaseB]);
            const ulonglong2* h1 =
                reinterpret_cast<const ulonglong2*>(&hbuf[1][cur][kbaseB]);
#pragma unroll
            for (int j = 0; j < QPAIRS / 4; j++) {
                ulonglong2 hA0 = h0[2 * j];
                ulonglong2 hB0 = h0[2 * j + 1];
                ulonglong2 hA1 = h1[2 * j];
                ulonglong2 hB1 = h1[2 * j + 1];
                FMA2(p0, hA0.x, wpB[4 * j + 0]);
                FMA2(q0, hA1.x, wpB[4 * j + 0]);
                FMA2(p1, hA0.y, wpB[4 * j + 1]);
                FMA2(q1, hA1.y, wpB[4 * j + 1]);
                FMA2(p2, hB0.x, wpB[4 * j + 2]);
                FMA2(q2, hB1.x, wpB[4 * j + 2]);
                FMA2(p3, hB0.y, wpB[4 * j + 3]);
                FMA2(q3, hB1.y, wpB[4 * j + 3]);
            }
        }

        // reduce both streams
        float u0, u1, u2, u3, u4, u5, u6, u7;
        UNPACK2(u0, u1, p0); UNPACK2(u2, u3, p1);
        UNPACK2(u4, u5, p2); UNPACK2(u6, u7, p3);
        float s0 = ((u0 + u1) + (u2 + u3)) + ((u4 + u5) + (u6 + u7));
        UNPACK2(u0, u1, q0); UNPACK2(u2, u3, q1);
        UNPACK2(u4, u5, q2); UNPACK2(u6, u7, q3);
        float s1 = ((u0 + u1) + (u2 + u3)) + ((u4 + u5) + (u6 + u7));

        s0 += __shfl_xor_sync(0xffffffffu, s0, 1);
        s1 += __shfl_xor_sync(0xffffffffu, s1, 1);

        const int nxt = cur ^ 1;
        float v0 = fast_tanh(xpv0 + s0);
        float v1 = fast_tanh(xpv1 + s1);

        if (kh == 0) {
            hbuf[0][nxt][gcol] = v0;               // local halves for t+1
            hbuf[1][nxt][gcol] = v1;
        } else {
            if (t + 1 < TT) {
                uint32_t mbp = mb0_peer + 8u * (uint32_t)((t + 1) & 3);
                uint32_t d0 = hb_peer + (uint32_t)((0 * 2 + nxt) * HH + gcol) * 4u;
                uint32_t d1 = hb_peer + (uint32_t)((1 * 2 + nxt) * HH + gcol) * 4u;
                asm volatile(
                    "st.async.shared::cluster.mbarrier::complete_tx::bytes.b32 [%0], %1, [%2];"
                    :: "r"(d0), "f"(v0), "r"(mbp) : "memory");
                asm volatile(
                    "st.async.shared::cluster.mbarrier::complete_tx::bytes.b32 [%0], %1, [%2];"
                    :: "r"(d1), "f"(v1), "r"(mbp) : "memory");
            }
            orow0[t * HH + gcol] = v0;             // h_t to gmem
            orow1[t * HH + gcol] = v1;
        }

        // re-arm mbar[t&3] for reuse at t+4 (off the wake path)
        if (tid == 0) {
            asm volatile("mbarrier.arrive.expect_tx.shared.b64 _, [%0], %1;"
                         :: "r"(mb_t), "r"(1024) : "memory");
        }
        __syncthreads();                           // local halves published

        cur = nxt;
        xpv0 = xn0;
        xpv1 = xn1;
    }

    // teardown: keep smem alive until the peer is fully done
    asm volatile("barrier.cluster.arrive.aligned;" ::: "memory");
    asm volatile("barrier.cluster.wait.aligned;" ::: "memory");
}

// ---------------------------------------------------------------------------
extern "C" void kernel_launch(void* const* d_in, const int* in_sizes, int n_in,
                              void* d_out, int out_size)
{
    const float* x    = (const float*)d_in[0];
    const float* Wxh  = (const float*)d_in[1];
    const float* Whh  = (const float*)d_in[2];
    const float* bias = (const float*)d_in[3];
    float* out = (float*)d_out;

    const int M = in_sizes[0] / DD;   // B*T

    dim3 gridA(M / BM, HH / BN);
    xp_gemm_kernel<<<gridA, 256>>>(x, Wxh, bias, out);

    // 32 clusters x 2 CTAs; each cluster runs 2 batch elements
    rnn_rec_kernel<<<BATCH, 256>>>(Whh, out);
}

// round 17
// speedup vs baseline: 2.4707x; 1.4442x over previous
#include <cuda_runtime.h>
#include <cstdint>

// Problem shape (fixed)
#define BATCH 64
#define TT    2048
#define DD    256
#define HH    256

// Packed fp32x2 ops (sm_100+ PTX; ptxas never emits these from C++)
#define FMA2(acc, a, b) \
    asm("fma.rn.f32x2 %0, %1, %2, %0;" : "+l"(acc) : "l"(a), "l"(b))
#define SPLAT2(dst, s) \
    asm("mov.b64 %0, {%1, %1};" : "=l"(dst) : "f"(s))
#define PACK2(dst, lo, hi) \
    asm("mov.b64 %0, {%1, %2};" : "=l"(dst) : "f"(lo), "f"(hi))
#define UNPACK2(lo, hi, src) \
    asm("mov.b64 {%0, %1}, %2;" : "=f"(lo), "=f"(hi) : "l"(src))

__device__ __forceinline__ uint32_t smem_u32(const void* p) {
    uint32_t a;
    asm("{ .reg .u64 t; cvta.to.shared.u64 t, %1; cvt.u32.u64 %0, t; }"
        : "=r"(a) : "l"(p));
    return a;
}

// Fast tanh: v = 1 - 2/(e^{2x}+1). MUFU-based, branch-free, saturates to +-1.
__device__ __forceinline__ float fast_tanh(float x) {
    float e = __expf(2.0f * x);
    return 1.0f - __fdividef(2.0f, e + 1.0f);
}

// ---------------------------------------------------------------------------
// Kernel A: xp = x @ Wxh + bias   (M=B*T, K=D, N=H), f32x2 inner product
// ---------------------------------------------------------------------------
#define BM 128
#define BN 128
#define BK 8
#define TM 8
#define TN 8

__global__ __launch_bounds__(256) void xp_gemm_kernel(
    const float* __restrict__ X,
    const float* __restrict__ W,
    const float* __restrict__ bias,
    float* __restrict__ out)
{
    __shared__ float As[BK][BM];
    __shared__ __align__(16) float Bs[BK][BN];

    const int m0 = blockIdx.x * BM;
    const int n0 = blockIdx.y * BN;
    const int tid = threadIdx.x;
    const int tx = tid & 15;   // N
    const int ty = tid >> 4;   // M

    const int a_r = tid >> 1;
    const int a_k = (tid & 1) * 4;
    const int b_r = tid >> 5;
    const int b_n = (tid & 31) * 4;

    unsigned long long acc[TM][TN / 2];
#pragma unroll
    for (int i = 0; i < TM; i++)
#pragma unroll
        for (int j = 0; j < TN / 2; j++) acc[i][j] = 0ull;

    const float* Xp = X + (long long)m0 * DD;

    for (int k0 = 0; k0 < DD; k0 += BK) {
        float4 av = *reinterpret_cast<const float4*>(Xp + (long long)a_r * DD + k0 + a_k);
        As[a_k + 0][a_r] = av.x;
        As[a_k + 1][a_r] = av.y;
        As[a_k + 2][a_r] = av.z;
        As[a_k + 3][a_r] = av.w;
        float4 bv = *reinterpret_cast<const float4*>(W + (long long)(k0 + b_r) * HH + n0 + b_n);
        *reinterpret_cast<float4*>(&Bs[b_r][b_n]) = bv;
        __syncthreads();

#pragma unroll
        for (int k = 0; k < BK; k++) {
            ulonglong2 b01 = *reinterpret_cast<const ulonglong2*>(&Bs[k][tx * TN]);
            ulonglong2 b23 = *reinterpret_cast<const ulonglong2*>(&Bs[k][tx * TN + 4]);
            float ar[TM];
#pragma unroll
            for (int i = 0; i < TM; i++) ar[i] = As[k][ty * TM + i];
#pragma unroll
            for (int i = 0; i < TM; i++) {
                unsigned long long ai;
                SPLAT2(ai, ar[i]);
                FMA2(acc[i][0], ai, b01.x);
                FMA2(acc[i][1], ai, b01.y);
                FMA2(acc[i][2], ai, b23.x);
                FMA2(acc[i][3], ai, b23.y);
            }
        }
        __syncthreads();
    }

    float bv[TN];
#pragma unroll
    for (int j = 0; j < TN; j++) bv[j] = bias[n0 + tx * TN + j];

#pragma unroll
    for (int i = 0; i < TM; i++) {
        const int row = m0 + ty * TM + i;
        float* op = out + (long long)row * HH + n0 + tx * TN;
        float r[TN];
#pragma unroll
        for (int j = 0; j < TN / 2; j++) {
            UNPACK2(r[2 * j], r[2 * j + 1], acc[i][j]);
        }
        float4 r0, r1;
        r0.x = r[0] + bv[0]; r0.y = r[1] + bv[1];
        r0.z = r[2] + bv[2]; r0.w = r[3] + bv[3];
        r1.x = r[4] + bv[4]; r1.y = r[5] + bv[5];
        r1.z = r[6] + bv[6]; r1.w = r[7] + bv[7];
        *reinterpret_cast<float4*>(op)     = r0;
        *reinterpret_cast<float4*>(op + 4) = r1;
    }
}

// ---------------------------------------------------------------------------
// Kernel B: recurrence on a 2-CTA cluster per batch element.
//   rank r owns output columns [r*128, (r+1)*128)
//   512 threads: col = tid>>2 (0..127), kh = tid&3 — 4-way k-split with
//   32-BYTE INTERLEAVE (fix of R14's 128B-stride bank aliasing):
//     thread kh owns rows { half + kh*8 + 32*g + i : g=0..3, i=0..7 }
//   Within one LDS.128, the 4 kh lanes hit 4 addresses 32B apart ->
//   distinct banks, conflict-free; the 4 segments tile the 128B line.
//   Weights: 16 pairs (phase A) + 16 pairs (phase B) = 64 regs; cap 128.
//
// Cross-CTA sync: st.async + mbarrier complete_tx (R12-proven protocol).
//   - 4 mbarriers; mbar[t&3] guards the peer half of hbuf[t&1] for step t.
//   - kh2 threads (128 of them) st.async h_{t+1} into the peer's
//     hbuf[(t+1)&1], 4B tx each -> 512B total.
//   - tid0 re-arms mbar[t&3] for reuse at t+4; mbars 1..3 pre-armed,
//     mbar[0] armed at t=0 (first completion t=4, phase 0).
//   - PARITY: mbar[i!=0] first completes at t=i (ph0) -> par=(t>>2)&1.
//             mbar[0]   first completes at t=4 (ph0) -> par=((t>>2)+1)&1.
// Per step: PhaseA (overlaps peer store flight) -> wait -> PhaseB ->
//   2x shfl combine -> fast_tanh -> stores (kh0 local / kh1 gmem /
//   kh2 st.async) -> arm -> syncthreads.
// ---------------------------------------------------------------------------

__global__ __launch_bounds__(512, 1) __cluster_dims__(2, 1, 1)
void rnn_rec_kernel(
    const float* __restrict__ Whh,
    float* __restrict__ out)
{
    __shared__ __align__(16) float hbuf[2][HH];
    __shared__ __align__(8) unsigned long long mbars[4];

    const int tid = threadIdx.x;
    const int c   = tid >> 2;
    const int kh  = tid & 3;
    uint32_t rank;
    asm("mov.u32 %0, %%cluster_ctarank;" : "=r"(rank));
    const int batch = blockIdx.x >> 1;
    const int gcol  = (int)rank * 128 + c;

    // interleaved slice bases (float offsets into h)
    const int koffA = (int)rank * 128 + kh * 8;          // local half
    const int koffB = (int)(rank ^ 1u) * 128 + kh * 8;   // peer half

    // ---- one-time: register-resident Whh slices ----
    // wpX[4g+p] packs rows (koffX + 32g + 2p, +1), g=0..3, p=0..3
    unsigned long long wpA[16], wpB[16];
#pragma unroll
    for (int g = 0; g < 4; g++) {
#pragma unroll
        for (int p = 0; p < 4; p++) {
            int rA = koffA + 32 * g + 2 * p;
            float a0 = Whh[(rA + 0) * HH + gcol];
            float a1 = Whh[(rA + 1) * HH + gcol];
            PACK2(wpA[4 * g + p], a0, a1);
            int rB = koffB + 32 * g + 2 * p;
            float b0 = Whh[(rB + 0) * HH + gcol];
            float b1 = Whh[(rB + 1) * HH + gcol];
            PACK2(wpB[4 * g + p], b0, b1);
        }
    }

    const uint32_t mb0_local = smem_u32(&mbars[0]);
    const uint32_t hb_local  = smem_u32(&hbuf[0][0]);

    if (tid == 0) {
#pragma unroll
        for (int i = 0; i < 4; i++) {
            asm volatile("mbarrier.init.shared.b64 [%0], %1;"
                         :: "r"(mb0_local + 8u * i), "r"(1) : "memory");
        }
        // pre-arm mbars for t=1,2,3; mbar[0] armed in-loop at t=0
#pragma unroll
        for (int i = 1; i < 4; i++) {
            asm volatile("mbarrier.arrive.expect_tx.shared.b64 _, [%0], %1;"
                         :: "r"(mb0_local + 8u * i), "r"(512) : "memory");
        }
    }
    if (tid < HH) hbuf[0][tid] = 0.f;
    __syncthreads();
    asm volatile("barrier.cluster.arrive.aligned;" ::: "memory");
    asm volatile("barrier.cluster.wait.aligned;" ::: "memory");

    uint32_t mb0_peer, hb_peer;
    {
        uint32_t peer = rank ^ 1u;
        asm("mapa.shared::cluster.u32 %0, %1, %2;"
            : "=r"(mb0_peer) : "r"(mb0_local), "r"(peer));
        asm("mapa.shared::cluster.u32 %0, %1, %2;"
            : "=r"(hb_peer) : "r"(hb_local), "r"(peer));
    }

    float* orow = out + (long long)batch * TT * HH;
    float xpv = orow[gcol];
    int cur = 0;

#pragma unroll 1
    for (int t = 0; t < TT; t++) {
        float xnext = 0.f;
        if (t + 1 < TT) xnext = orow[(t + 1) * HH + gcol];

        unsigned long long a0 = 0ull, a1 = 0ull, a2 = 0ull, a3 = 0ull;

        // ---- Phase A: local interleaved quarter (overlaps store flight) ---
        {
            const float* hbase = &hbuf[cur][koffA];
#pragma unroll
            for (int g = 0; g < 4; g++) {
                const ulonglong2* h2 =
                    reinterpret_cast<const ulonglong2*>(hbase + 32 * g);
                ulonglong2 hA = h2[0];
                ulonglong2 hB = h2[1];
                FMA2(a0, hA.x, wpA[4 * g + 0]);
                FMA2(a1, hA.y, wpA[4 * g + 1]);
                FMA2(a2, hB.x, wpA[4 * g + 2]);
                FMA2(a3, hB.y, wpA[4 * g + 3]);
            }
        }

        // ---- wait: peer half of h_t landed (tx complete). t=0: local init.
        const uint32_t mb_t = mb0_local + 8u * (uint32_t)(t & 3);
        if (t > 0) {
            const uint32_t q = (uint32_t)(t >> 2);
            const uint32_t par = ((t & 3) == 0) ? ((q + 1) & 1u) : (q & 1u);
            uint32_t done;
            asm volatile(
                "{\n\t.reg .pred p;\n\t"
                "mbarrier.try_wait.parity.acquire.cluster.shared::cta.b64 p, [%1], %2;\n\t"
                "selp.b32 %0, 1, 0, p;\n\t}"
                : "=r"(done) : "r"(mb_t), "r"(par) : "memory");
            if (!done) {
                asm volatile(
                    "{\n\t.reg .pred P1;\n\t"
                    "WL_%=:\n\t"
                    "mbarrier.try_wait.parity.acquire.cluster.shared::cta.b64 P1, [%0], %1, 0x989680;\n\t"
                    "@P1 bra.uni WD_%=;\n\t"
                    "bra.uni WL_%=;\n\t"
                    "WD_%=:\n\t}"
                    :: "r"(mb_t), "r"(par) : "memory");
            }
        }

        // ---- Phase B: peer interleaved quarter ----
        {
            const float* hbase = &hbuf[cur][koffB];
#pragma unroll
            for (int g = 0; g < 4; g++) {
                const ulonglong2* h2 =
                    reinterpret_cast<const ulonglong2*>(hbase + 32 * g);
                ulonglong2 hA = h2[0];
                ulonglong2 hB = h2[1];
                FMA2(a0, hA.x, wpB[4 * g + 0]);
                FMA2(a1, hA.y, wpB[4 * g + 1]);
                FMA2(a2, hB.x, wpB[4 * g + 2]);
                FMA2(a3, hB.y, wpB[4 * g + 3]);
            }
        }

        float s0, s1, s2, s3, s4, s5, s6, s7;
        UNPACK2(s0, s1, a0);
        UNPACK2(s2, s3, a1);
        UNPACK2(s4, s5, a2);
        UNPACK2(s6, s7, a3);
        float s = ((s0 + s1) + (s2 + s3)) + ((s4 + s5) + (s6 + s7));
        // combine the 4 kh lanes (adjacent lanes of one warp)
        s += __shfl_xor_sync(0xffffffffu, s, 1);
        s += __shfl_xor_sync(0xffffffffu, s, 2);

        const int nxt = cur ^ 1;
        float v = fast_tanh(xpv + s);

        if (kh == 0) {
            hbuf[nxt][gcol] = v;                   // local half for t+1
        } else if (kh == 1) {
            orow[t * HH + gcol] = v;               // h_t to gmem
        } else if (kh == 2) {
            if (t + 1 < TT) {
                uint32_t dst = hb_peer + (uint32_t)(nxt * HH + gcol) * 4u;
                uint32_t mbp = mb0_peer + 8u * (uint32_t)((t + 1) & 3);
                asm volatile(
                    "st.async.shared::cluster.mbarrier::complete_tx::bytes.b32 [%0], %1, [%2];"
                    :: "r"(dst), "f"(v), "r"(mbp) : "memory");
            }
        }

        // re-arm mbar[t&3] for reuse at t+4 (off the wake path)
        if (tid == 0) {
            asm volatile("mbarrier.arrive.expect_tx.shared.b64 _, [%0], %1;"
                         :: "r"(mb_t), "r"(512) : "memory");
        }
        __syncthreads();                           // local half published

        cur = nxt;
        xpv = xnext;
    }

    // teardown: keep smem alive until the peer is fully done
    asm volatile("barrier.cluster.arrive.aligned;" ::: "memory");
    asm volatile("barrier.cluster.wait.aligned;" ::: "memory");
}

// ---------------------------------------------------------------------------
extern "C" void kernel_launch(void* const* d_in, const int* in_sizes, int n_in,
                              void* d_out, int out_size)
{
    const float* x    = (const float*)d_in[0];
    const float* Wxh  = (const float*)d_in[1];
    const float* Whh  = (const float*)d_in[2];
    const float* bias = (const float*)d_in[3];
    float* out = (float*)d_out;

    const int M = in_sizes[0] / DD;   // B*T

    dim3 gridA(M / BM, HH / BN);
    xp_gemm_kernel<<<gridA, 256>>>(x, Wxh, bias, out);

    rnn_rec_kernel<<<BATCH * 2, 512>>>(Whh, out);
}